// round 3
// baseline (speedup 1.0000x reference)
#include <cuda_runtime.h>
#include <cuda_bf16.h>
#include <cstdint>

#define BB 256
#define TT 128
#define FF 512
#define HH 1024
#define GG 4096

typedef unsigned long long ull;

// ---------- scratch (device globals; allocation is forbidden) ----------
__device__ float g_xproj[(size_t)TT * BB * GG];   // [T][B][4H]
__device__ float g_h[2][(size_t)BB * HH];
__device__ float g_c[2][(size_t)BB * HH];

// ---------- packed fp32 helpers ----------
__device__ __forceinline__ void fma2(ull& d, ull a, ull b) {
    asm("fma.rn.f32x2 %0, %1, %2, %0;" : "+l"(d) : "l"(a), "l"(b));
}
__device__ __forceinline__ ull dup2(float x) {
    ull r;
    asm("mov.b64 %0, {%1, %1};" : "=l"(r) : "r"(__float_as_int(x)));
    return r;
}
__device__ __forceinline__ float2 unpack2(ull v) {
    int lo, hi;
    asm("mov.b64 {%0, %1}, %2;" : "=r"(lo), "=r"(hi) : "l"(v));
    return make_float2(__int_as_float(lo), __int_as_float(hi));
}
__device__ __forceinline__ float sigf(float x) { return 1.0f / (1.0f + __expf(-x)); }

// 8 packed FMAs: two A rows x 8 output columns from one B stream tile
#define FMA_ST(acc, a0, a1, sptr) do {                                        \
    ulonglong2 q0 = *reinterpret_cast<const ulonglong2*>((sptr) + bo);        \
    ulonglong2 q1 = *reinterpret_cast<const ulonglong2*>((sptr) + bo + 4);    \
    fma2(acc[0], a0, q0.x); fma2(acc[1], a0, q0.y);                           \
    fma2(acc[2], a0, q1.x); fma2(acc[3], a0, q1.y);                           \
    fma2(acc[4], a1, q0.x); fma2(acc[5], a1, q0.y);                           \
    fma2(acc[6], a1, q1.x); fma2(acc[7], a1, q1.y); } while (0)

// ---------- init ----------
__global__ void zero_kernel() {
    int i = blockIdx.x * blockDim.x + threadIdx.x;
    if (i < BB * HH) { g_h[0][i] = 0.0f; g_c[0][i] = 0.0f; }
}

// ---------- x_proj = x @ W_x + b  -> [T][B][4H] ----------
// grid (64, 256), 256 threads. BM=128, BN=64, BK=32, TM=8, TN=4.
__global__ void __launch_bounds__(256) xproj_kernel(const float* __restrict__ x,
                                                    const float* __restrict__ Wx,
                                                    const float* __restrict__ bias) {
    __shared__ float sA[128 * 36];                 // [m][kk], pad 36 (16B aligned)
    __shared__ __align__(16) float sB[32 * 64];    // [kk][n]

    const int tid = threadIdx.x;
    const int col_id = tid & 15;   // 16 cols * TN=4
    const int row_id = tid >> 4;   // 16 rows * TM=8
    const int n0 = blockIdx.x * 64;
    const int m0 = blockIdx.y * 128;

    const int a_row = tid >> 3, a_kv = (tid & 7) << 2;       // + v*32 rows
    const int b_kk = tid >> 4, b_c4 = (tid & 15) << 2;       // + v*16 kk

    ull acc[16];
#pragma unroll
    for (int i = 0; i < 16; i++) acc[i] = 0ULL;

    float4 pa[4], pb[2];
#pragma unroll
    for (int v = 0; v < 4; v++)
        pa[v] = *reinterpret_cast<const float4*>(&x[(size_t)(m0 + a_row + v * 32) * FF + a_kv]);
#pragma unroll
    for (int v = 0; v < 2; v++)
        pb[v] = *reinterpret_cast<const float4*>(&Wx[(size_t)(b_kk + v * 16) * GG + n0 + b_c4]);

#pragma unroll 1
    for (int k0 = 0; k0 < FF; k0 += 32) {
        __syncthreads();
#pragma unroll
        for (int v = 0; v < 4; v++)
            *reinterpret_cast<float4*>(&sA[(a_row + v * 32) * 36 + a_kv]) = pa[v];
#pragma unroll
        for (int v = 0; v < 2; v++)
            *reinterpret_cast<float4*>(&sB[(b_kk + v * 16) * 64 + b_c4]) = pb[v];
        __syncthreads();

        const int kn = k0 + 32;
        if (kn < FF) {
#pragma unroll
            for (int v = 0; v < 4; v++)
                pa[v] = *reinterpret_cast<const float4*>(&x[(size_t)(m0 + a_row + v * 32) * FF + kn + a_kv]);
#pragma unroll
            for (int v = 0; v < 2; v++)
                pb[v] = *reinterpret_cast<const float4*>(&Wx[(size_t)(kn + b_kk + v * 16) * GG + n0 + b_c4]);
        }

#pragma unroll 4
        for (int kk = 0; kk < 32; kk++) {
            ulonglong2 q = *reinterpret_cast<const ulonglong2*>(&sB[kk * 64 + (col_id << 2)]);
#pragma unroll
            for (int i = 0; i < 8; i++) {
                ull ai = dup2(sA[(row_id * 8 + i) * 36 + kk]);
                fma2(acc[i * 2 + 0], ai, q.x);
                fma2(acc[i * 2 + 1], ai, q.y);
            }
        }
    }

    const int g = n0 + (col_id << 2);
    const float4 bv = *reinterpret_cast<const float4*>(&bias[g]);
#pragma unroll
    for (int i = 0; i < 8; i++) {
        int m = m0 + row_id * 8 + i;       // m = b*T + t  (x is [B,T,F], T=128)
        int t = m & (TT - 1);
        int b = m >> 7;
        float2 lo = unpack2(acc[i * 2 + 0]);
        float2 hi = unpack2(acc[i * 2 + 1]);
        float4 o;
        o.x = lo.x + bv.x; o.y = lo.y + bv.y;
        o.z = hi.x + bv.z; o.w = hi.y + bv.w;
        *reinterpret_cast<float4*>(&g_xproj[((size_t)t * BB + b) * GG + g]) = o;
    }
}

// ---------- step 1: c_new (gates f, i, c~) ----------
// grid (16, 8), 128 threads. BM=32, BN=64, BK=16, TM=2, TN=8. 5 fused streams.
__global__ void __launch_bounds__(128) step1_kernel(const float* __restrict__ Rh,
                                                    const float* __restrict__ Pf,
                                                    const float* __restrict__ Pi,
                                                    int t, int p) {
    __shared__ float sA[2 * 32 * 20];               // h then c, pad 20
    __shared__ __align__(16) float sB[5 * 16 * 64];

    const int tid = threadIdx.x;
    const int col_id = tid & 7;    // 8 cols * TN=8
    const int row_id = tid >> 3;   // 16 rows * TM=2
    const int j0 = blockIdx.x * 64;
    const int r0 = blockIdx.y * 32;

    const float* hb = g_h[p];
    const float* cb = g_c[p];

    const float* Bs0 = Rh + j0;            // f <- h   (ld GG)
    const float* Bs1 = Pf + j0;            // f <- c   (ld HH)
    const float* Bs2 = Rh + HH + j0;       // i <- h
    const float* Bs3 = Pi + j0;            // i <- c
    const float* Bs4 = Rh + 2 * HH + j0;   // c~ <- h

    const int am = tid >> 2, akv = (tid & 3) << 2;          // A stage
    const int bk0 = tid >> 4, bk1 = (tid >> 4) + 8;         // B stage
    const int bc4 = (tid & 15) << 2;

    ull accF[8], accI[8], accC[8];
#pragma unroll
    for (int i = 0; i < 8; i++) { accF[i] = 0ULL; accI[i] = 0ULL; accC[i] = 0ULL; }

    float4 ph, pc, pb[10];
    {
        const size_t ar = (size_t)(r0 + am) * HH + akv;
        ph = *reinterpret_cast<const float4*>(&hb[ar]);
        pc = *reinterpret_cast<const float4*>(&cb[ar]);
        pb[0] = *reinterpret_cast<const float4*>(&Bs0[(size_t)bk0 * GG + bc4]);
        pb[1] = *reinterpret_cast<const float4*>(&Bs0[(size_t)bk1 * GG + bc4]);
        pb[2] = *reinterpret_cast<const float4*>(&Bs1[(size_t)bk0 * HH + bc4]);
        pb[3] = *reinterpret_cast<const float4*>(&Bs1[(size_t)bk1 * HH + bc4]);
        pb[4] = *reinterpret_cast<const float4*>(&Bs2[(size_t)bk0 * GG + bc4]);
        pb[5] = *reinterpret_cast<const float4*>(&Bs2[(size_t)bk1 * GG + bc4]);
        pb[6] = *reinterpret_cast<const float4*>(&Bs3[(size_t)bk0 * HH + bc4]);
        pb[7] = *reinterpret_cast<const float4*>(&Bs3[(size_t)bk1 * HH + bc4]);
        pb[8] = *reinterpret_cast<const float4*>(&Bs4[(size_t)bk0 * GG + bc4]);
        pb[9] = *reinterpret_cast<const float4*>(&Bs4[(size_t)bk1 * GG + bc4]);
    }

#pragma unroll 1
    for (int k0 = 0; k0 < HH; k0 += 16) {
        __syncthreads();
        *reinterpret_cast<float4*>(&sA[am * 20 + akv]) = ph;
        *reinterpret_cast<float4*>(&sA[640 + am * 20 + akv]) = pc;
#pragma unroll
        for (int s = 0; s < 5; s++) {
            *reinterpret_cast<float4*>(&sB[s * 1024 + bk0 * 64 + bc4]) = pb[s * 2 + 0];
            *reinterpret_cast<float4*>(&sB[s * 1024 + bk1 * 64 + bc4]) = pb[s * 2 + 1];
        }
        __syncthreads();

        const int kn = k0 + 16;
        if (kn < HH) {
            const size_t ar = (size_t)(r0 + am) * HH + kn + akv;
            ph = *reinterpret_cast<const float4*>(&hb[ar]);
            pc = *reinterpret_cast<const float4*>(&cb[ar]);
            pb[0] = *reinterpret_cast<const float4*>(&Bs0[(size_t)(kn + bk0) * GG + bc4]);
            pb[1] = *reinterpret_cast<const float4*>(&Bs0[(size_t)(kn + bk1) * GG + bc4]);
            pb[2] = *reinterpret_cast<const float4*>(&Bs1[(size_t)(kn + bk0) * HH + bc4]);
            pb[3] = *reinterpret_cast<const float4*>(&Bs1[(size_t)(kn + bk1) * HH + bc4]);
            pb[4] = *reinterpret_cast<const float4*>(&Bs2[(size_t)(kn + bk0) * GG + bc4]);
            pb[5] = *reinterpret_cast<const float4*>(&Bs2[(size_t)(kn + bk1) * GG + bc4]);
            pb[6] = *reinterpret_cast<const float4*>(&Bs3[(size_t)(kn + bk0) * HH + bc4]);
            pb[7] = *reinterpret_cast<const float4*>(&Bs3[(size_t)(kn + bk1) * HH + bc4]);
            pb[8] = *reinterpret_cast<const float4*>(&Bs4[(size_t)(kn + bk0) * GG + bc4]);
            pb[9] = *reinterpret_cast<const float4*>(&Bs4[(size_t)(kn + bk1) * GG + bc4]);
        }

#pragma unroll 4
        for (int kk = 0; kk < 16; kk++) {
            ull ah0 = dup2(sA[(row_id * 2 + 0) * 20 + kk]);
            ull ah1 = dup2(sA[(row_id * 2 + 1) * 20 + kk]);
            ull ac0 = dup2(sA[640 + (row_id * 2 + 0) * 20 + kk]);
            ull ac1 = dup2(sA[640 + (row_id * 2 + 1) * 20 + kk]);
            const int bo = kk * 64 + (col_id << 3);
            FMA_ST(accF, ah0, ah1, sB);
            FMA_ST(accF, ac0, ac1, sB + 1024);
            FMA_ST(accI, ah0, ah1, sB + 2048);
            FMA_ST(accI, ac0, ac1, sB + 3072);
            FMA_ST(accC, ah0, ah1, sB + 4096);
        }
    }

    float* cn = g_c[1 ^ p];
#pragma unroll
    for (int mi = 0; mi < 2; mi++) {
        int r = r0 + row_id * 2 + mi;
        const float* xp = g_xproj + ((size_t)t * BB + r) * GG;
        const float* crow = cb + (size_t)r * HH;
        float* cnrow = cn + (size_t)r * HH;
#pragma unroll
        for (int nq = 0; nq < 4; nq++) {
            int j = j0 + (col_id << 3) + nq * 2;
            float2 f2 = unpack2(accF[mi * 4 + nq]);
            float2 i2 = unpack2(accI[mi * 4 + nq]);
            float2 c2 = unpack2(accC[mi * 4 + nq]);
            float2 xf = *reinterpret_cast<const float2*>(&xp[j]);
            float2 xi = *reinterpret_cast<const float2*>(&xp[HH + j]);
            float2 xc = *reinterpret_cast<const float2*>(&xp[2 * HH + j]);
            float2 co = *reinterpret_cast<const float2*>(&crow[j]);
            float2 o;
            o.x = co.x * sigf(f2.x + xf.x) + tanhf(c2.x + xc.x) * sigf(i2.x + xi.x);
            o.y = co.y * sigf(f2.y + xf.y) + tanhf(c2.y + xc.y) * sigf(i2.y + xi.y);
            *reinterpret_cast<float2*>(&cnrow[j]) = o;
        }
    }
}

// ---------- step 2: h_new (gate o) ----------
__global__ void __launch_bounds__(128) step2_kernel(const float* __restrict__ Rh,
                                                    const float* __restrict__ Po,
                                                    int t, int p, float* dst_override) {
    __shared__ float sA[2 * 32 * 20];
    __shared__ __align__(16) float sB[2 * 16 * 64];

    const int tid = threadIdx.x;
    const int col_id = tid & 7;
    const int row_id = tid >> 3;
    const int j0 = blockIdx.x * 64;
    const int r0 = blockIdx.y * 32;

    const float* hb = g_h[p];
    const float* cn = g_c[1 ^ p];

    const float* Bs0 = Rh + 3 * HH + j0;   // o <- h     (ld GG)
    const float* Bs1 = Po + j0;            // o <- c_new (ld HH)

    const int am = tid >> 2, akv = (tid & 3) << 2;
    const int bk0 = tid >> 4, bk1 = (tid >> 4) + 8;
    const int bc4 = (tid & 15) << 2;

    ull accO[8];
#pragma unroll
    for (int i = 0; i < 8; i++) accO[i] = 0ULL;

    float4 ph, pc, pb[4];
    {
        const size_t ar = (size_t)(r0 + am) * HH + akv;
        ph = *reinterpret_cast<const float4*>(&hb[ar]);
        pc = *reinterpret_cast<const float4*>(&cn[ar]);
        pb[0] = *reinterpret_cast<const float4*>(&Bs0[(size_t)bk0 * GG + bc4]);
        pb[1] = *reinterpret_cast<const float4*>(&Bs0[(size_t)bk1 * GG + bc4]);
        pb[2] = *reinterpret_cast<const float4*>(&Bs1[(size_t)bk0 * HH + bc4]);
        pb[3] = *reinterpret_cast<const float4*>(&Bs1[(size_t)bk1 * HH + bc4]);
    }

#pragma unroll 1
    for (int k0 = 0; k0 < HH; k0 += 16) {
        __syncthreads();
        *reinterpret_cast<float4*>(&sA[am * 20 + akv]) = ph;
        *reinterpret_cast<float4*>(&sA[640 + am * 20 + akv]) = pc;
        *reinterpret_cast<float4*>(&sB[bk0 * 64 + bc4]) = pb[0];
        *reinterpret_cast<float4*>(&sB[bk1 * 64 + bc4]) = pb[1];
        *reinterpret_cast<float4*>(&sB[1024 + bk0 * 64 + bc4]) = pb[2];
        *reinterpret_cast<float4*>(&sB[1024 + bk1 * 64 + bc4]) = pb[3];
        __syncthreads();

        const int kn = k0 + 16;
        if (kn < HH) {
            const size_t ar = (size_t)(r0 + am) * HH + kn + akv;
            ph = *reinterpret_cast<const float4*>(&hb[ar]);
            pc = *reinterpret_cast<const float4*>(&cn[ar]);
            pb[0] = *reinterpret_cast<const float4*>(&Bs0[(size_t)(kn + bk0) * GG + bc4]);
            pb[1] = *reinterpret_cast<const float4*>(&Bs0[(size_t)(kn + bk1) * GG + bc4]);
            pb[2] = *reinterpret_cast<const float4*>(&Bs1[(size_t)(kn + bk0) * HH + bc4]);
            pb[3] = *reinterpret_cast<const float4*>(&Bs1[(size_t)(kn + bk1) * HH + bc4]);
        }

#pragma unroll 4
        for (int kk = 0; kk < 16; kk++) {
            ull ah0 = dup2(sA[(row_id * 2 + 0) * 20 + kk]);
            ull ah1 = dup2(sA[(row_id * 2 + 1) * 20 + kk]);
            ull ac0 = dup2(sA[640 + (row_id * 2 + 0) * 20 + kk]);
            ull ac1 = dup2(sA[640 + (row_id * 2 + 1) * 20 + kk]);
            const int bo = kk * 64 + (col_id << 3);
            FMA_ST(accO, ah0, ah1, sB);
            FMA_ST(accO, ac0, ac1, sB + 1024);
        }
    }

    float* hdst = dst_override ? dst_override : g_h[1 ^ p];
#pragma unroll
    for (int mi = 0; mi < 2; mi++) {
        int r = r0 + row_id * 2 + mi;
        const float* xp = g_xproj + ((size_t)t * BB + r) * GG;
        const float* cnrow = cn + (size_t)r * HH;
        float* hrow = hdst + (size_t)r * HH;
#pragma unroll
        for (int nq = 0; nq < 4; nq++) {
            int j = j0 + (col_id << 3) + nq * 2;
            float2 o2 = unpack2(accO[mi * 4 + nq]);
            float2 xo = *reinterpret_cast<const float2*>(&xp[3 * HH + j]);
            float2 cv = *reinterpret_cast<const float2*>(&cnrow[j]);
            float2 o;
            o.x = tanhf(cv.x) * sigf(o2.x + xo.x);
            o.y = tanhf(cv.y) * sigf(o2.y + xo.y);
            *reinterpret_cast<float2*>(&hrow[j]) = o;
        }
    }
}

// ---------- launch ----------
extern "C" void kernel_launch(void* const* d_in, const int* in_sizes, int n_in,
                              void* d_out, int out_size) {
    const float* x  = (const float*)d_in[0];
    const float* Wx = (const float*)d_in[1];
    const float* b  = (const float*)d_in[2];
    const float* Rh = (const float*)d_in[3];
    const float* Pf = (const float*)d_in[4];
    const float* Pi = (const float*)d_in[5];
    const float* Po = (const float*)d_in[6];
    float* out = (float*)d_out;

    zero_kernel<<<(BB * HH + 255) / 256, 256>>>();
    xproj_kernel<<<dim3(64, 256), 256>>>(x, Wx, b);

    dim3 sgrid(16, 8);
    for (int t = 0; t < TT; t++) {
        int p = t & 1;
        step1_kernel<<<sgrid, 128>>>(Rh, Pf, Pi, t, p);
        step2_kernel<<<sgrid, 128>>>(Rh, Po, t, p, (t == TT - 1) ? out : nullptr);
    }
}

// round 4
// speedup vs baseline: 2.1889x; 2.1889x over previous
#include <cuda_runtime.h>
#include <cuda_bf16.h>
#include <cstdint>

#define BB 256
#define TT 128
#define FF 512
#define HH 1024
#define GG 4096

typedef unsigned long long ull;

// ---------- scratch (device globals; allocation is forbidden) ----------
__device__ float g_xproj[(size_t)TT * BB * GG];   // [T][B][4H]
__device__ float g_h[2][(size_t)BB * HH];
__device__ float g_c[2][(size_t)BB * HH];
__device__ float g_go[(size_t)BB * HH];           // x_o + h@Rh_o (per step)

// ---------- packed fp32 helpers ----------
__device__ __forceinline__ void fma2(ull& d, ull a, ull b) {
    asm("fma.rn.f32x2 %0, %1, %2, %0;" : "+l"(d) : "l"(a), "l"(b));
}
__device__ __forceinline__ ull dup2(float x) {
    ull r;
    asm("mov.b64 %0, {%1, %1};" : "=l"(r) : "r"(__float_as_int(x)));
    return r;
}
__device__ __forceinline__ float2 unpack2(ull v) {
    int lo, hi;
    asm("mov.b64 {%0, %1}, %2;" : "=r"(lo), "=r"(hi) : "l"(v));
    return make_float2(__int_as_float(lo), __int_as_float(hi));
}
__device__ __forceinline__ float sigf(float x) { return 1.0f / (1.0f + __expf(-x)); }
__device__ __forceinline__ float4 ld4(const float* p) {
    return *reinterpret_cast<const float4*>(p);
}
__device__ __forceinline__ void st4(float* p, float4 v) {
    *reinterpret_cast<float4*>(p) = v;
}

// ---------- init ----------
__global__ void zero_kernel() {
    int i = blockIdx.x * blockDim.x + threadIdx.x;
    if (i < BB * HH) { g_h[0][i] = 0.0f; g_c[0][i] = 0.0f; }
}

// ---------- x_proj = x @ W_x + b  -> [T][B][4H] ----------
// grid (64, 256), 256 threads. BM=128, BN=64, BK=32, TM=8, TN=4.
__global__ void __launch_bounds__(256) xproj_kernel(const float* __restrict__ x,
                                                    const float* __restrict__ Wx,
                                                    const float* __restrict__ bias) {
    __shared__ float sA[128 * 36];
    __shared__ __align__(16) float sB[32 * 64];

    const int tid = threadIdx.x;
    const int col_id = tid & 15;
    const int row_id = tid >> 4;
    const int n0 = blockIdx.x * 64;
    const int m0 = blockIdx.y * 128;

    const int a_row = tid >> 3, a_kv = (tid & 7) << 2;
    const int b_kk = tid >> 4, b_c4 = (tid & 15) << 2;

    ull acc[16];
#pragma unroll
    for (int i = 0; i < 16; i++) acc[i] = 0ULL;

    float4 pa[4], pb[2];
#pragma unroll
    for (int v = 0; v < 4; v++)
        pa[v] = ld4(&x[(size_t)(m0 + a_row + v * 32) * FF + a_kv]);
#pragma unroll
    for (int v = 0; v < 2; v++)
        pb[v] = ld4(&Wx[(size_t)(b_kk + v * 16) * GG + n0 + b_c4]);

#pragma unroll 1
    for (int k0 = 0; k0 < FF; k0 += 32) {
        __syncthreads();
#pragma unroll
        for (int v = 0; v < 4; v++)
            st4(&sA[(a_row + v * 32) * 36 + a_kv], pa[v]);
#pragma unroll
        for (int v = 0; v < 2; v++)
            st4(&sB[(b_kk + v * 16) * 64 + b_c4], pb[v]);
        __syncthreads();

        const int kn = k0 + 32;
        if (kn < FF) {
#pragma unroll
            for (int v = 0; v < 4; v++)
                pa[v] = ld4(&x[(size_t)(m0 + a_row + v * 32) * FF + kn + a_kv]);
#pragma unroll
            for (int v = 0; v < 2; v++)
                pb[v] = ld4(&Wx[(size_t)(kn + b_kk + v * 16) * GG + n0 + b_c4]);
        }

#pragma unroll 4
        for (int kk = 0; kk < 32; kk++) {
            ulonglong2 q = *reinterpret_cast<const ulonglong2*>(&sB[kk * 64 + (col_id << 2)]);
#pragma unroll
            for (int i = 0; i < 8; i++) {
                ull ai = dup2(sA[(row_id * 8 + i) * 36 + kk]);
                fma2(acc[i * 2 + 0], ai, q.x);
                fma2(acc[i * 2 + 1], ai, q.y);
            }
        }
    }

    const int g = n0 + (col_id << 2);
    const float4 bv = ld4(&bias[g]);
#pragma unroll
    for (int i = 0; i < 8; i++) {
        int m = m0 + row_id * 8 + i;       // m = b*T + t  (x is [B,T,F])
        int t = m & (TT - 1);
        int b = m >> 7;
        float2 lo = unpack2(acc[i * 2 + 0]);
        float2 hi = unpack2(acc[i * 2 + 1]);
        float4 o;
        o.x = lo.x + bv.x; o.y = lo.y + bv.y;
        o.z = hi.x + bv.z; o.w = hi.y + bv.w;
        st4(&g_xproj[((size_t)t * BB + b) * GG + g], o);
    }
}

// ---------- step 1: c_new + go_part (streams f,i,c~,o from h; f,i from c) ----------
// grid (32, 8) = 256 CTAs, 128 threads. BM=32, BN=32, BK=32, TM=4, TN=2.
__global__ void __launch_bounds__(128) step1_kernel(const float* __restrict__ Rh,
                                                    const float* __restrict__ Pf,
                                                    const float* __restrict__ Pi,
                                                    int t, int p) {
    __shared__ float sAh[32 * 36];                  // h tile [row][k], pad 36
    __shared__ float sAc[32 * 36];                  // c tile
    __shared__ __align__(16) float sB[6 * 32 * 32]; // 6 streams [kk][n]

    const int tid = threadIdx.x;
    const int col_id = tid & 15;   // 16 cols * TN=2
    const int row_id = tid >> 4;   // 8 rows * TM=4
    const int j0 = blockIdx.x * 32;
    const int r0 = blockIdx.y * 32;

    const float* hb = g_h[p];
    const float* cb = g_c[p];

    const float* Bs0 = Rh + 0 * HH + j0;   // f  <- h  (ld GG)
    const float* Bs1 = Rh + 1 * HH + j0;   // i  <- h
    const float* Bs2 = Rh + 2 * HH + j0;   // c~ <- h
    const float* Bs3 = Rh + 3 * HH + j0;   // o  <- h
    const float* Bs4 = Pf + j0;            // f  <- c  (ld HH)
    const float* Bs5 = Pi + j0;            // i  <- c

    // staging indices: 2 float4 per array per thread
    const int ar0 = tid >> 3, ar1 = ar0 + 16;       // rows
    const int akc = (tid & 7) << 2;                 // k col (float4)
    const int bk0 = tid >> 3, bk1 = bk0 + 16;       // kk rows
    const int bc = (tid & 7) << 2;                  // n col (float4)

    ull accF[4], accI[4], accC[4], accO[4];
#pragma unroll
    for (int i = 0; i < 4; i++) { accF[i] = 0ULL; accI[i] = 0ULL; accC[i] = 0ULL; accO[i] = 0ULL; }

    float4 ph[2], pc[2], pb[12];
    {
        ph[0] = ld4(&hb[(size_t)(r0 + ar0) * HH + akc]);
        ph[1] = ld4(&hb[(size_t)(r0 + ar1) * HH + akc]);
        pc[0] = ld4(&cb[(size_t)(r0 + ar0) * HH + akc]);
        pc[1] = ld4(&cb[(size_t)(r0 + ar1) * HH + akc]);
        pb[0]  = ld4(&Bs0[(size_t)bk0 * GG + bc]);  pb[1]  = ld4(&Bs0[(size_t)bk1 * GG + bc]);
        pb[2]  = ld4(&Bs1[(size_t)bk0 * GG + bc]);  pb[3]  = ld4(&Bs1[(size_t)bk1 * GG + bc]);
        pb[4]  = ld4(&Bs2[(size_t)bk0 * GG + bc]);  pb[5]  = ld4(&Bs2[(size_t)bk1 * GG + bc]);
        pb[6]  = ld4(&Bs3[(size_t)bk0 * GG + bc]);  pb[7]  = ld4(&Bs3[(size_t)bk1 * GG + bc]);
        pb[8]  = ld4(&Bs4[(size_t)bk0 * HH + bc]);  pb[9]  = ld4(&Bs4[(size_t)bk1 * HH + bc]);
        pb[10] = ld4(&Bs5[(size_t)bk0 * HH + bc]);  pb[11] = ld4(&Bs5[(size_t)bk1 * HH + bc]);
    }

#pragma unroll 1
    for (int k0 = 0; k0 < HH; k0 += 32) {
        __syncthreads();
        st4(&sAh[ar0 * 36 + akc], ph[0]);
        st4(&sAh[ar1 * 36 + akc], ph[1]);
        st4(&sAc[ar0 * 36 + akc], pc[0]);
        st4(&sAc[ar1 * 36 + akc], pc[1]);
#pragma unroll
        for (int s = 0; s < 6; s++) {
            st4(&sB[s * 1024 + bk0 * 32 + bc], pb[s * 2 + 0]);
            st4(&sB[s * 1024 + bk1 * 32 + bc], pb[s * 2 + 1]);
        }
        __syncthreads();

        const int kn = k0 + 32;
        if (kn < HH) {
            ph[0] = ld4(&hb[(size_t)(r0 + ar0) * HH + kn + akc]);
            ph[1] = ld4(&hb[(size_t)(r0 + ar1) * HH + kn + akc]);
            pc[0] = ld4(&cb[(size_t)(r0 + ar0) * HH + kn + akc]);
            pc[1] = ld4(&cb[(size_t)(r0 + ar1) * HH + kn + akc]);
            pb[0]  = ld4(&Bs0[(size_t)(kn + bk0) * GG + bc]);  pb[1]  = ld4(&Bs0[(size_t)(kn + bk1) * GG + bc]);
            pb[2]  = ld4(&Bs1[(size_t)(kn + bk0) * GG + bc]);  pb[3]  = ld4(&Bs1[(size_t)(kn + bk1) * GG + bc]);
            pb[4]  = ld4(&Bs2[(size_t)(kn + bk0) * GG + bc]);  pb[5]  = ld4(&Bs2[(size_t)(kn + bk1) * GG + bc]);
            pb[6]  = ld4(&Bs3[(size_t)(kn + bk0) * GG + bc]);  pb[7]  = ld4(&Bs3[(size_t)(kn + bk1) * GG + bc]);
            pb[8]  = ld4(&Bs4[(size_t)(kn + bk0) * HH + bc]);  pb[9]  = ld4(&Bs4[(size_t)(kn + bk1) * HH + bc]);
            pb[10] = ld4(&Bs5[(size_t)(kn + bk0) * HH + bc]);  pb[11] = ld4(&Bs5[(size_t)(kn + bk1) * HH + bc]);
        }

#pragma unroll 8
        for (int kk = 0; kk < 32; kk++) {
            ull ah[4], ac[4];
#pragma unroll
            for (int mi = 0; mi < 4; mi++) {
                ah[mi] = dup2(sAh[(row_id * 4 + mi) * 36 + kk]);
                ac[mi] = dup2(sAc[(row_id * 4 + mi) * 36 + kk]);
            }
            const int bo = kk * 32 + (col_id << 1);
            ull bF = *reinterpret_cast<const ull*>(&sB[0 * 1024 + bo]);
            ull bI = *reinterpret_cast<const ull*>(&sB[1 * 1024 + bo]);
            ull bC = *reinterpret_cast<const ull*>(&sB[2 * 1024 + bo]);
            ull bO = *reinterpret_cast<const ull*>(&sB[3 * 1024 + bo]);
            ull bPf = *reinterpret_cast<const ull*>(&sB[4 * 1024 + bo]);
            ull bPi = *reinterpret_cast<const ull*>(&sB[5 * 1024 + bo]);
#pragma unroll
            for (int mi = 0; mi < 4; mi++) {
                fma2(accF[mi], ah[mi], bF);
                fma2(accI[mi], ah[mi], bI);
                fma2(accC[mi], ah[mi], bC);
                fma2(accO[mi], ah[mi], bO);
                fma2(accF[mi], ac[mi], bPf);
                fma2(accI[mi], ac[mi], bPi);
            }
        }
    }

    float* cn = g_c[1 ^ p];
    const int j = j0 + (col_id << 1);
#pragma unroll
    for (int mi = 0; mi < 4; mi++) {
        int r = r0 + row_id * 4 + mi;
        const float* xp = g_xproj + ((size_t)t * BB + r) * GG;
        float2 f2 = unpack2(accF[mi]);
        float2 i2 = unpack2(accI[mi]);
        float2 c2 = unpack2(accC[mi]);
        float2 o2 = unpack2(accO[mi]);
        float2 xf = *reinterpret_cast<const float2*>(&xp[j]);
        float2 xi = *reinterpret_cast<const float2*>(&xp[HH + j]);
        float2 xc = *reinterpret_cast<const float2*>(&xp[2 * HH + j]);
        float2 xo = *reinterpret_cast<const float2*>(&xp[3 * HH + j]);
        float2 co = *reinterpret_cast<const float2*>(&cb[(size_t)r * HH + j]);
        float2 cv, gv;
        cv.x = co.x * sigf(f2.x + xf.x) + tanhf(c2.x + xc.x) * sigf(i2.x + xi.x);
        cv.y = co.y * sigf(f2.y + xf.y) + tanhf(c2.y + xc.y) * sigf(i2.y + xi.y);
        gv.x = o2.x + xo.x;
        gv.y = o2.y + xo.y;
        *reinterpret_cast<float2*>(&cn[(size_t)r * HH + j]) = cv;
        *reinterpret_cast<float2*>(&g_go[(size_t)r * HH + j]) = gv;
    }
}

// ---------- step 2: h_new = tanh(c_new) * sigmoid(go_part + c_new @ P_o) ----------
// grid (32, 8) = 256 CTAs, 128 threads. BM=32, BN=32, BK=32, TM=4, TN=2. 1 stream.
__global__ void __launch_bounds__(128) step2_kernel(const float* __restrict__ Po,
                                                    int p, float* dst_override) {
    __shared__ float sAc[32 * 36];
    __shared__ __align__(16) float sB[32 * 32];

    const int tid = threadIdx.x;
    const int col_id = tid & 15;
    const int row_id = tid >> 4;
    const int j0 = blockIdx.x * 32;
    const int r0 = blockIdx.y * 32;

    const float* cn = g_c[1 ^ p];
    const float* Bs = Po + j0;             // ld HH

    const int ar0 = tid >> 3, ar1 = ar0 + 16;
    const int akc = (tid & 7) << 2;
    const int bk0 = tid >> 3, bk1 = bk0 + 16;
    const int bc = (tid & 7) << 2;

    ull accO[4];
#pragma unroll
    for (int i = 0; i < 4; i++) accO[i] = 0ULL;

    float4 pa[2], pq[2];
    {
        pa[0] = ld4(&cn[(size_t)(r0 + ar0) * HH + akc]);
        pa[1] = ld4(&cn[(size_t)(r0 + ar1) * HH + akc]);
        pq[0] = ld4(&Bs[(size_t)bk0 * HH + bc]);
        pq[1] = ld4(&Bs[(size_t)bk1 * HH + bc]);
    }

#pragma unroll 1
    for (int k0 = 0; k0 < HH; k0 += 32) {
        __syncthreads();
        st4(&sAc[ar0 * 36 + akc], pa[0]);
        st4(&sAc[ar1 * 36 + akc], pa[1]);
        st4(&sB[bk0 * 32 + bc], pq[0]);
        st4(&sB[bk1 * 32 + bc], pq[1]);
        __syncthreads();

        const int kn = k0 + 32;
        if (kn < HH) {
            pa[0] = ld4(&cn[(size_t)(r0 + ar0) * HH + kn + akc]);
            pa[1] = ld4(&cn[(size_t)(r0 + ar1) * HH + kn + akc]);
            pq[0] = ld4(&Bs[(size_t)(kn + bk0) * HH + bc]);
            pq[1] = ld4(&Bs[(size_t)(kn + bk1) * HH + bc]);
        }

#pragma unroll 16
        for (int kk = 0; kk < 32; kk++) {
            const int bo = kk * 32 + (col_id << 1);
            ull bq = *reinterpret_cast<const ull*>(&sB[bo]);
#pragma unroll
            for (int mi = 0; mi < 4; mi++) {
                ull a = dup2(sAc[(row_id * 4 + mi) * 36 + kk]);
                fma2(accO[mi], a, bq);
            }
        }
    }

    float* hdst = dst_override ? dst_override : g_h[1 ^ p];
    const int j = j0 + (col_id << 1);
#pragma unroll
    for (int mi = 0; mi < 4; mi++) {
        int r = r0 + row_id * 4 + mi;
        float2 o2 = unpack2(accO[mi]);
        float2 gv = *reinterpret_cast<const float2*>(&g_go[(size_t)r * HH + j]);
        float2 cv = *reinterpret_cast<const float2*>(&cn[(size_t)r * HH + j]);
        float2 hv;
        hv.x = tanhf(cv.x) * sigf(o2.x + gv.x);
        hv.y = tanhf(cv.y) * sigf(o2.y + gv.y);
        *reinterpret_cast<float2*>(&hdst[(size_t)r * HH + j]) = hv;
    }
}

// ---------- launch ----------
extern "C" void kernel_launch(void* const* d_in, const int* in_sizes, int n_in,
                              void* d_out, int out_size) {
    const float* x  = (const float*)d_in[0];
    const float* Wx = (const float*)d_in[1];
    const float* b  = (const float*)d_in[2];
    const float* Rh = (const float*)d_in[3];
    const float* Pf = (const float*)d_in[4];
    const float* Pi = (const float*)d_in[5];
    const float* Po = (const float*)d_in[6];
    float* out = (float*)d_out;

    zero_kernel<<<(BB * HH + 255) / 256, 256>>>();
    xproj_kernel<<<dim3(64, 256), 256>>>(x, Wx, b);

    dim3 sgrid(32, 8);
    for (int t = 0; t < TT; t++) {
        int p = t & 1;
        step1_kernel<<<sgrid, 128>>>(Rh, Pf, Pi, t, p);
        step2_kernel<<<sgrid, 128>>>(Po, p, (t == TT - 1) ? out : nullptr);
    }
}